// round 1
// baseline (speedup 1.0000x reference)
#include <cuda_runtime.h>
#include <stdint.h>

// Problem: SparseLaplacianBuilder  (2E=1.6M edges, d=4, n=50000)
// Output layout (float32): [ idx0[M] | idx1[M] | vals[M] ],  M = 16n + 32E.

#define N_MAX   65536
#define E_MAX   1048576            // half-edge count E
#define ITEMS_MAX (N_MAX + 2*E_MAX)
#define SORT_MAX 1024

// Static scratch (no allocation allowed in kernel_launch)
__device__ float              g_diag[(size_t)N_MAX * 16];     // 4 MB
__device__ float              g_P[(size_t)E_MAX * 16];        // 64 MB
__device__ unsigned int       g_deg[N_MAX];
__device__ unsigned int       g_cursor[N_MAX];
__device__ unsigned int       g_itemoff[N_MAX + 1];
__device__ unsigned long long g_items[ITEMS_MAX];
__device__ unsigned long long g_items2[ITEMS_MAX];            // fallback sort buffer

// key = (target << 22) | (class << 20) | e      class: 0=diag, 1=ij, 2=ji

__global__ void k_zero(int n) {
    int i = blockIdx.x * blockDim.x + threadIdx.x;
    if (i < n * 16) g_diag[i] = 0.f;
    if (i < n)      g_deg[i]  = 0u;
}

// One thread handles edge pair (e, E+e): Gram matrices -> diag atomics,
// P[e] = L^T R, degree counts from first-half (row, col).
__global__ void k_edge(const float* __restrict__ maps, const int* __restrict__ ei,
                       int E, int twoE) {
    int e = blockIdx.x * blockDim.x + threadIdx.x;
    if (e >= E) return;

    float L[16], R[16];
    const float4* Lp = reinterpret_cast<const float4*>(maps + (size_t)e * 16);
    const float4* Rp = reinterpret_cast<const float4*>(maps + (size_t)(E + e) * 16);
#pragma unroll
    for (int k = 0; k < 4; k++) {
        float4 v = Lp[k];
        L[k*4+0] = v.x; L[k*4+1] = v.y; L[k*4+2] = v.z; L[k*4+3] = v.w;
        float4 w = Rp[k];
        R[k*4+0] = w.x; R[k*4+1] = w.y; R[k*4+2] = w.z; R[k*4+3] = w.w;
    }

    int nL  = ei[e];          // edge_index[0][e]   == row
    int nR  = ei[E + e];      // edge_index[0][E+e]
    int col = ei[twoE + e];   // edge_index[1][e]

    float* dL = &g_diag[(size_t)nL * 16];
    float* dR = &g_diag[(size_t)nR * 16];
    float Pv[16];
#pragma unroll
    for (int a = 0; a < 4; a++) {
#pragma unroll
        for (int b = 0; b < 4; b++) {
            float gl = 0.f, gr = 0.f, p = 0.f;
#pragma unroll
            for (int k = 0; k < 4; k++) {
                gl += L[k*4+a] * L[k*4+b];
                gr += R[k*4+a] * R[k*4+b];
                p  += L[k*4+a] * R[k*4+b];
            }
            atomicAdd(dL + a*4 + b, gl);
            atomicAdd(dR + a*4 + b, gr);
            Pv[a*4+b] = p;
        }
    }
    float4* Pp = reinterpret_cast<float4*>(&g_P[(size_t)e * 16]);
#pragma unroll
    for (int k = 0; k < 4; k++)
        Pp[k] = make_float4(Pv[k*4], Pv[k*4+1], Pv[k*4+2], Pv[k*4+3]);

    atomicAdd(&g_deg[nL],  1u);
    atomicAdd(&g_deg[col], 1u);
}

// Single-block exclusive scan of (1 + deg[u]) into g_itemoff (n up to N_MAX).
__global__ void k_scan(int n) {
    __shared__ unsigned int s[1024];
    __shared__ unsigned int carry;
    if (threadIdx.x == 0) carry = 0u;
    __syncthreads();
    for (int base = 0; base < n; base += 1024) {
        int i = base + (int)threadIdx.x;
        unsigned x = (i < n) ? (1u + g_deg[i]) : 0u;
        s[threadIdx.x] = x;
        __syncthreads();
        for (int off = 1; off < 1024; off <<= 1) {
            unsigned v = (threadIdx.x >= (unsigned)off) ? s[threadIdx.x - off] : 0u;
            __syncthreads();
            s[threadIdx.x] += v;
            __syncthreads();
        }
        unsigned c = carry;
        if (i < n) g_itemoff[i] = c + s[threadIdx.x] - x;   // exclusive
        __syncthreads();
        if (threadIdx.x == 1023) carry = c + s[1023];
        __syncthreads();
    }
    if (threadIdx.x == 0) g_itemoff[n] = carry;
}

__global__ void k_diag_item(int n) {
    int u = blockIdx.x * blockDim.x + threadIdx.x;
    if (u >= n) return;
    g_items[g_itemoff[u]] = ((unsigned long long)u) << 22;   // class 0, e = 0
    g_cursor[u] = 1u;
}

__global__ void k_edge_item(const int* __restrict__ ei, int E, int twoE) {
    int e = blockIdx.x * blockDim.x + threadIdx.x;
    if (e >= E) return;
    int row = ei[e];
    int col = ei[twoE + e];
    unsigned p1 = g_itemoff[row] + atomicAdd(&g_cursor[row], 1u);
    g_items[p1] = (((unsigned long long)col) << 22) | (1ull << 20) | (unsigned)e;
    unsigned p2 = g_itemoff[col] + atomicAdd(&g_cursor[col], 1u);
    g_items[p2] = (((unsigned long long)row) << 22) | (2ull << 20) | (unsigned)e;
}

// Warp per node: bitonic sort of its item list, then expand to 16 entries/item.
__global__ void k_sort_expand(float* __restrict__ out, int n, size_t M) {
    __shared__ unsigned long long skeys[4][SORT_MAX];
    int wi   = blockIdx.x * 4 + ((int)threadIdx.x >> 5);
    int lane = (int)threadIdx.x & 31;
    if (wi >= n) return;

    unsigned beg = g_itemoff[wi];
    unsigned end = g_itemoff[wi + 1];
    int cnt = (int)(end - beg);

    unsigned long long* keys;
    if (cnt <= SORT_MAX) {
        unsigned long long* sk = skeys[(int)threadIdx.x >> 5];
        for (int i = lane; i < cnt; i += 32) sk[i] = g_items[beg + i];
        int P2 = 1; while (P2 < cnt) P2 <<= 1;
        for (int i = cnt + lane; i < P2; i += 32) sk[i] = ~0ull;
        __syncwarp();
        for (int k = 2; k <= P2; k <<= 1) {
            for (int j = k >> 1; j > 0; j >>= 1) {
                for (int i = lane; i < P2; i += 32) {
                    int ixj = i ^ j;
                    if (ixj > i) {
                        unsigned long long A = sk[i], B = sk[ixj];
                        bool asc = ((i & k) == 0);
                        if (asc ? (A > B) : (A < B)) { sk[i] = B; sk[ixj] = A; }
                    }
                }
                __syncwarp();
            }
        }
        keys = sk;
    } else {
        // O(cnt^2) rank sort fallback (never expected for this data)
        for (int jj = lane; jj < cnt; jj += 32) {
            unsigned long long kj = g_items[beg + jj];
            int r = 0;
            for (int k2 = 0; k2 < cnt; k2++) r += (g_items[beg + k2] < kj);
            g_items2[beg + r] = kj;
        }
        __syncwarp();
        keys = &g_items2[beg];
    }

    float* idx0 = out;
    float* idx1 = out + M;
    float* vals = out + 2 * M;
    size_t nodebase = (size_t)beg * 16;
    int fourcnt = 4 * cnt;
    int tot = 16 * cnt;

    for (int w = lane; w < tot; w += 32) {
        int a = w / fourcnt;
        int r = w - a * fourcnt;
        int t = r >> 2;
        int b = r & 3;
        unsigned long long key = keys[t];
        unsigned tgt = (unsigned)(key >> 22);
        unsigned cls = ((unsigned)(key >> 20)) & 3u;
        unsigned e   = (unsigned)(key & 0xFFFFFu);
        // run of equal targets -> stable lexsort grouping by j
        int g0 = t; while (g0 > 0 && (unsigned)(keys[g0 - 1] >> 22) == tgt) g0--;
        int g1 = t; while (g1 + 1 < cnt && (unsigned)(keys[g1 + 1] >> 22) == tgt) g1++;
        int len = g1 - g0 + 1;
        int posrow = 4 * g0 + b * len + (t - g0);
        size_t pos = nodebase + (size_t)a * fourcnt + posrow;

        float v;
        if (cls == 0)      v =  g_diag[(size_t)wi * 16 + a * 4 + b];
        else if (cls == 1) v = -g_P[(size_t)e * 16 + a * 4 + b];
        else               v = -g_P[(size_t)e * 16 + b * 4 + a];

        idx0[pos] = (float)(wi * 4 + a);
        idx1[pos] = (float)(tgt * 4 + b);
        vals[pos] = v;
    }
}

extern "C" void kernel_launch(void* const* d_in, const int* in_sizes, int n_in,
                              void* d_out, int out_size) {
    const float* maps = (const float*)d_in[0];
    const int*   ei   = (const int*)d_in[1];

    int twoE = in_sizes[0] / 16;
    int E    = twoE / 2;
    size_t M = (size_t)out_size / 3;                      // total COO entries
    int n    = (int)((M - (size_t)twoE * 16) / 16);       // 16n + 16*twoE = M

    float* out = (float*)d_out;
    const int B = 256;

    k_zero<<<(n * 16 + B - 1) / B, B>>>(n);
    k_edge<<<(E + B - 1) / B, B>>>(maps, ei, E, twoE);
    k_scan<<<1, 1024>>>(n);
    k_diag_item<<<(n + B - 1) / B, B>>>(n);
    k_edge_item<<<(E + B - 1) / B, B>>>(ei, E, twoE);
    k_sort_expand<<<(n + 3) / 4, 128>>>(out, n, M);
}

// round 2
// speedup vs baseline: 1.8391x; 1.8391x over previous
#include <cuda_runtime.h>
#include <stdint.h>

// SparseLaplacianBuilder: 2E=1.6M, d=4, n=50000.
// Output (float32): [ idx0[M] | idx1[M] | vals[M] ], M = 16n + 32E.
//
// Per-node item decomposition: each node u owns 1 diag item + deg(u) edge items,
// sorted by key (target<<22 | class<<20 | e), then expanded x16 (a,b) with
// equal-target runs interleaved b-major to reproduce the stable lexsort order.

#define N_MAX     65536
#define E_MAX     1048576
#define ITEMS_MAX (N_MAX + 2*E_MAX)
#define SORT_MAX  256
#define NB_MAX    64            // scan blocks: N_MAX/1024

__device__ float              g_diag[(size_t)N_MAX * 16];
__device__ float              g_P[(size_t)E_MAX * 16];
__device__ unsigned int       g_deg[N_MAX];          // zero-init; re-zeroed each run
__device__ unsigned int       g_cursor[N_MAX];
__device__ unsigned int       g_itemoff[N_MAX + 1];
__device__ unsigned int       g_blktot[NB_MAX];
__device__ unsigned int       g_blkoff[NB_MAX];
__device__ unsigned long long g_items[ITEMS_MAX];
__device__ unsigned long long g_items2[ITEMS_MAX];   // fallback sort buffer

// ---------- 1. degree counts (g_deg must be 0 on entry; restored by k_sort_expand) ----------
__global__ void k_deg(const int* __restrict__ ei, int E, int twoE) {
    int e = blockIdx.x * blockDim.x + threadIdx.x;
    if (e >= E) return;
    atomicAdd(&g_deg[ei[e]], 1u);          // row side (class ij)
    atomicAdd(&g_deg[ei[twoE + e]], 1u);   // col side (class ji)
}

// ---------- 2. per-block scan of (1+deg) + zero g_diag ----------
__global__ void k_scan_blocks(int n) {
    __shared__ unsigned int s[1024];
    int i = blockIdx.x * 1024 + (int)threadIdx.x;
    unsigned x = (i < n) ? (1u + g_deg[i]) : 0u;
    s[threadIdx.x] = x;
    __syncthreads();
#pragma unroll
    for (int off = 1; off < 1024; off <<= 1) {
        unsigned v = (threadIdx.x >= (unsigned)off) ? s[threadIdx.x - off] : 0u;
        __syncthreads();
        s[threadIdx.x] += v;
        __syncthreads();
    }
    if (i < n) {
        g_itemoff[i] = s[threadIdx.x] - x;   // local exclusive
        float4 z = make_float4(0.f, 0.f, 0.f, 0.f);
        float4* d = reinterpret_cast<float4*>(&g_diag[(size_t)i * 16]);
        d[0] = z; d[1] = z; d[2] = z; d[3] = z;
    }
    if (threadIdx.x == 1023) g_blktot[blockIdx.x] = s[1023];
}

// ---------- 3. scan block totals (nb <= 64) ----------
__global__ void k_scan_tot(int nb, int n) {
    __shared__ unsigned int s[NB_MAX];
    int t = (int)threadIdx.x;          // blockDim = 64
    unsigned x = (t < nb) ? g_blktot[t] : 0u;
    s[t] = x;
    __syncthreads();
#pragma unroll
    for (int off = 1; off < NB_MAX; off <<= 1) {
        unsigned v = (t >= off) ? s[t - off] : 0u;
        __syncthreads();
        s[t] += v;
        __syncthreads();
    }
    if (t < nb) g_blkoff[t] = s[t] - x;
    if (t == nb - 1) g_itemoff[n] = s[t];    // grand total
}

// ---------- 4. finalize offsets + diag item + cursor init ----------
__global__ void k_finalize(int n) {
    int i = blockIdx.x * blockDim.x + (int)threadIdx.x;
    if (i >= n) return;
    unsigned off = g_itemoff[i] + g_blkoff[i >> 10];
    g_itemoff[i] = off;
    g_items[off] = ((unsigned long long)i) << 22;   // class 0 (diag), e = 0
    g_cursor[i]  = 1u;
}

// ---------- 5. edge pass: Gram atomics + P = L^T R + item scatter ----------
__global__ void k_edge_all(const float* __restrict__ maps, const int* __restrict__ ei,
                           int E, int twoE) {
    int e = blockIdx.x * blockDim.x + threadIdx.x;
    if (e >= E) return;

    float L[16], R[16];
    const float4* Lp = reinterpret_cast<const float4*>(maps + (size_t)e * 16);
    const float4* Rp = reinterpret_cast<const float4*>(maps + (size_t)(E + e) * 16);
#pragma unroll
    for (int k = 0; k < 4; k++) {
        float4 v = Lp[k];
        L[k*4+0] = v.x; L[k*4+1] = v.y; L[k*4+2] = v.z; L[k*4+3] = v.w;
        float4 w = Rp[k];
        R[k*4+0] = w.x; R[k*4+1] = w.y; R[k*4+2] = w.z; R[k*4+3] = w.w;
    }

    int row = ei[e];          // edge_index[0][e]
    int nR  = ei[E + e];      // edge_index[0][E+e] (diag target only)
    int col = ei[twoE + e];   // edge_index[1][e]

    float* dL = &g_diag[(size_t)row * 16];
    float* dR = &g_diag[(size_t)nR * 16];
    float Pv[16];
#pragma unroll
    for (int a = 0; a < 4; a++) {
#pragma unroll
        for (int b = 0; b < 4; b++) {
            float gl = 0.f, gr = 0.f, p = 0.f;
#pragma unroll
            for (int k = 0; k < 4; k++) {
                gl += L[k*4+a] * L[k*4+b];
                gr += R[k*4+a] * R[k*4+b];
                p  += L[k*4+a] * R[k*4+b];
            }
            atomicAdd(dL + a*4 + b, gl);
            atomicAdd(dR + a*4 + b, gr);
            Pv[a*4+b] = p;
        }
    }
    float4* Pp = reinterpret_cast<float4*>(&g_P[(size_t)e * 16]);
#pragma unroll
    for (int k = 0; k < 4; k++)
        Pp[k] = make_float4(Pv[k*4], Pv[k*4+1], Pv[k*4+2], Pv[k*4+3]);

    unsigned p1 = g_itemoff[row] + atomicAdd(&g_cursor[row], 1u);
    g_items[p1] = (((unsigned long long)col) << 22) | (1ull << 20) | (unsigned)e;
    unsigned p2 = g_itemoff[col] + atomicAdd(&g_cursor[col], 1u);
    g_items[p2] = (((unsigned long long)row) << 22) | (2ull << 20) | (unsigned)e;
}

// ---------- 6. warp-per-node bitonic sort + expansion ----------
__global__ void __launch_bounds__(256, 8) k_sort_expand(float* __restrict__ out, int n, size_t M) {
    __shared__ unsigned long long skeys[8][SORT_MAX];
    __shared__ unsigned int       sruns[8][SORT_MAX];
    int warp = (int)threadIdx.x >> 5;
    int lane = (int)threadIdx.x & 31;
    int wi   = blockIdx.x * 8 + warp;
    if (wi >= n) return;

    if (lane == 0) g_deg[wi] = 0u;      // restore invariant for next run

    unsigned beg = g_itemoff[wi];
    unsigned end = g_itemoff[wi + 1];
    int cnt = (int)(end - beg);

    float* idx0 = out;
    float* idx1 = out + M;
    float* vals = out + 2 * M;
    size_t nodebase = (size_t)beg * 16;
    int fourcnt = cnt << 2;
    float fbase = (float)(wi << 2);

    if (cnt <= SORT_MAX) {
        unsigned long long* sk = skeys[warp];
        unsigned int*       sr = sruns[warp];
        for (int i = lane; i < cnt; i += 32) sk[i] = g_items[beg + i];
        int P2 = 1; while (P2 < cnt) P2 <<= 1;
        for (int i = cnt + lane; i < P2; i += 32) sk[i] = ~0ull;
        __syncwarp();
        for (int k = 2; k <= P2; k <<= 1) {
            for (int j = k >> 1; j > 0; j >>= 1) {
                for (int i = lane; i < P2; i += 32) {
                    int ixj = i ^ j;
                    if (ixj > i) {
                        unsigned long long A = sk[i], B = sk[ixj];
                        bool asc = ((i & k) == 0);
                        if (asc ? (A > B) : (A < B)) { sk[i] = B; sk[ixj] = A; }
                    }
                }
                __syncwarp();
            }
        }
        // precompute per-item run info: base = 4*g0 + (t-g0), len (packed)
        for (int t = lane; t < cnt; t += 32) {
            unsigned tgt = (unsigned)(sk[t] >> 22);
            int g0 = t; while (g0 > 0 && (unsigned)(sk[g0 - 1] >> 22) == tgt) g0--;
            int g1 = t; while (g1 + 1 < cnt && (unsigned)(sk[g1 + 1] >> 22) == tgt) g1++;
            sr[t] = ((unsigned)((g0 << 2) + (t - g0)) << 9) | (unsigned)(g1 - g0 + 1);
        }
        __syncwarp();

#pragma unroll
        for (int a = 0; a < 4; a++) {
            float fi = fbase + (float)a;
            size_t rowbase = nodebase + (size_t)a * fourcnt;
            int aoff = a << 2;
            for (int r = lane; r < fourcnt; r += 32) {
                int t = r >> 2, b = r & 3;
                unsigned long long key = sk[t];
                unsigned run = sr[t];
                int posrow = (int)(run >> 9) + b * (int)(run & 511u);
                unsigned tgt = (unsigned)(key >> 22);
                unsigned cls = ((unsigned)(key >> 20)) & 3u;
                unsigned e   = (unsigned)key & 0xFFFFFu;
                float v;
                if (cls == 0)      v =  g_diag[((size_t)wi << 4) + aoff + b];
                else if (cls == 1) v = -g_P[((size_t)e << 4) + aoff + b];
                else               v = -g_P[((size_t)e << 4) + (b << 2) + a];
                size_t pos = rowbase + posrow;
                idx0[pos] = fi;
                idx1[pos] = (float)((tgt << 2) + b);
                vals[pos] = v;
            }
        }
    } else {
        // cold fallback: O(cnt^2) rank sort in global, run-scan per element
        for (int jj = lane; jj < cnt; jj += 32) {
            unsigned long long kj = g_items[beg + jj];
            int rk = 0;
            for (int k2 = 0; k2 < cnt; k2++) rk += (g_items[beg + k2] < kj);
            g_items2[beg + rk] = kj;
        }
        __syncwarp();
        const unsigned long long* keys = &g_items2[beg];
#pragma unroll
        for (int a = 0; a < 4; a++) {
            float fi = fbase + (float)a;
            size_t rowbase = nodebase + (size_t)a * fourcnt;
            int aoff = a << 2;
            for (int r = lane; r < fourcnt; r += 32) {
                int t = r >> 2, b = r & 3;
                unsigned long long key = keys[t];
                unsigned tgt = (unsigned)(key >> 22);
                unsigned cls = ((unsigned)(key >> 20)) & 3u;
                unsigned e   = (unsigned)key & 0xFFFFFu;
                int g0 = t; while (g0 > 0 && (unsigned)(keys[g0 - 1] >> 22) == tgt) g0--;
                int g1 = t; while (g1 + 1 < cnt && (unsigned)(keys[g1 + 1] >> 22) == tgt) g1++;
                int len = g1 - g0 + 1;
                int posrow = (g0 << 2) + b * len + (t - g0);
                float v;
                if (cls == 0)      v =  g_diag[((size_t)wi << 4) + aoff + b];
                else if (cls == 1) v = -g_P[((size_t)e << 4) + aoff + b];
                else               v = -g_P[((size_t)e << 4) + (b << 2) + a];
                size_t pos = rowbase + posrow;
                idx0[pos] = fi;
                idx1[pos] = (float)((tgt << 2) + b);
                vals[pos] = v;
            }
        }
    }
}

extern "C" void kernel_launch(void* const* d_in, const int* in_sizes, int n_in,
                              void* d_out, int out_size) {
    const float* maps = (const float*)d_in[0];
    const int*   ei   = (const int*)d_in[1];

    int twoE = in_sizes[0] / 16;
    int E    = twoE / 2;
    size_t M = (size_t)out_size / 3;
    int n    = (int)((M - (size_t)twoE * 16) / 16);
    int nb   = (n + 1023) / 1024;

    float* out = (float*)d_out;
    const int B = 256;

    k_deg        <<<(E + B - 1) / B, B>>>(ei, E, twoE);
    k_scan_blocks<<<nb, 1024>>>(n);
    k_scan_tot   <<<1, NB_MAX>>>(nb, n);
    k_finalize   <<<(n + B - 1) / B, B>>>(n);
    k_edge_all   <<<(E + B - 1) / B, B>>>(maps, ei, E, twoE);
    k_sort_expand<<<(n + 7) / 8, 256>>>(out, n, M);
}

// round 3
// speedup vs baseline: 2.5698x; 1.3973x over previous
#include <cuda_runtime.h>
#include <stdint.h>

// SparseLaplacianBuilder: 2E=1.6M, d=4, n=50000.
// Output (float32): [ idx0[M] | idx1[M] | vals[M] ], M = 16n + 32E.

#define N_MAX     65536
#define E_MAX     1048576
#define ITEMS_MAX (N_MAX + 2*E_MAX)
#define NB_MAX    64

__device__ float              g_diag[(size_t)N_MAX * 16];   // upper triangle only (lower = 0)
__device__ float              g_P[(size_t)E_MAX * 16];
__device__ unsigned int       g_deg[N_MAX];                 // zero-init; restored each run
__device__ unsigned int       g_cursor[N_MAX];
__device__ unsigned int       g_itemoff[N_MAX + 1];
__device__ unsigned int       g_blktot[NB_MAX];
__device__ unsigned int       g_blkoff[NB_MAX];
__device__ unsigned long long g_items[ITEMS_MAX];
__device__ unsigned long long g_items2[ITEMS_MAX];          // cold fallback buffer

// key = (target << 22) | (class << 20) | e      class: 0=diag, 1=ij, 2=ji

// ---------- 1. degree counts ----------
__global__ void k_deg(const int* __restrict__ ei, int E, int twoE) {
    int e = blockIdx.x * blockDim.x + threadIdx.x;
    if (e >= E) return;
    atomicAdd(&g_deg[ei[e]], 1u);
    atomicAdd(&g_deg[ei[twoE + e]], 1u);
}

// ---------- 2. per-block scan of (1+deg) + zero g_diag ----------
__global__ void k_scan_blocks(int n) {
    __shared__ unsigned int s[1024];
    int i = blockIdx.x * 1024 + (int)threadIdx.x;
    unsigned x = (i < n) ? (1u + g_deg[i]) : 0u;
    s[threadIdx.x] = x;
    __syncthreads();
#pragma unroll
    for (int off = 1; off < 1024; off <<= 1) {
        unsigned v = (threadIdx.x >= (unsigned)off) ? s[threadIdx.x - off] : 0u;
        __syncthreads();
        s[threadIdx.x] += v;
        __syncthreads();
    }
    if (i < n) {
        g_itemoff[i] = s[threadIdx.x] - x;
        float4 z = make_float4(0.f, 0.f, 0.f, 0.f);
        float4* d = reinterpret_cast<float4*>(&g_diag[(size_t)i * 16]);
        d[0] = z; d[1] = z; d[2] = z; d[3] = z;
    }
    if (threadIdx.x == 1023) g_blktot[blockIdx.x] = s[1023];
}

// ---------- 3. scan of block totals ----------
__global__ void k_scan_tot(int nb, int n) {
    __shared__ unsigned int s[NB_MAX];
    int t = (int)threadIdx.x;
    unsigned x = (t < nb) ? g_blktot[t] : 0u;
    s[t] = x;
    __syncthreads();
#pragma unroll
    for (int off = 1; off < NB_MAX; off <<= 1) {
        unsigned v = (t >= off) ? s[t - off] : 0u;
        __syncthreads();
        s[t] += v;
        __syncthreads();
    }
    if (t < nb) g_blkoff[t] = s[t] - x;
    if (t == nb - 1) g_itemoff[n] = s[t];
}

// ---------- 4. finalize offsets + diag item + cursor ----------
__global__ void k_finalize(int n) {
    int i = blockIdx.x * blockDim.x + (int)threadIdx.x;
    if (i >= n) return;
    unsigned off = g_itemoff[i] + g_blkoff[i >> 10];
    g_itemoff[i] = off;
    g_items[off] = ((unsigned long long)i) << 22;
    g_cursor[i]  = 1u;
}

// ---------- 5. edge pass: upper-triangle Gram atomics + P + item scatter ----------
__global__ void k_edge_all(const float* __restrict__ maps, const int* __restrict__ ei,
                           int E, int twoE) {
    int e = blockIdx.x * blockDim.x + threadIdx.x;
    if (e >= E) return;

    float L[16], R[16];
    const float4* Lp = reinterpret_cast<const float4*>(maps + (size_t)e * 16);
    const float4* Rp = reinterpret_cast<const float4*>(maps + (size_t)(E + e) * 16);
#pragma unroll
    for (int k = 0; k < 4; k++) {
        float4 v = Lp[k];
        L[k*4+0] = v.x; L[k*4+1] = v.y; L[k*4+2] = v.z; L[k*4+3] = v.w;
        float4 w = Rp[k];
        R[k*4+0] = w.x; R[k*4+1] = w.y; R[k*4+2] = w.z; R[k*4+3] = w.w;
    }

    int row = ei[e];
    int nR  = ei[E + e];
    int col = ei[twoE + e];

    float* dL = &g_diag[(size_t)row * 16];
    float* dR = &g_diag[(size_t)nR * 16];
#pragma unroll
    for (int a = 0; a < 4; a++) {
#pragma unroll
        for (int b = a; b < 4; b++) {            // symmetric: upper triangle only
            float gl = 0.f, gr = 0.f;
#pragma unroll
            for (int k = 0; k < 4; k++) {
                gl += L[k*4+a] * L[k*4+b];
                gr += R[k*4+a] * R[k*4+b];
            }
            atomicAdd(dL + a*4 + b, gl);
            atomicAdd(dR + a*4 + b, gr);
        }
    }
    float Pv[16];
#pragma unroll
    for (int a = 0; a < 4; a++)
#pragma unroll
        for (int b = 0; b < 4; b++) {
            float p = 0.f;
#pragma unroll
            for (int k = 0; k < 4; k++) p += L[k*4+a] * R[k*4+b];
            Pv[a*4+b] = p;
        }
    float4* Pp = reinterpret_cast<float4*>(&g_P[(size_t)e * 16]);
#pragma unroll
    for (int k = 0; k < 4; k++)
        Pp[k] = make_float4(Pv[k*4], Pv[k*4+1], Pv[k*4+2], Pv[k*4+3]);

    unsigned p1 = g_itemoff[row] + atomicAdd(&g_cursor[row], 1u);
    g_items[p1] = (((unsigned long long)col) << 22) | (1ull << 20) | (unsigned)e;
    unsigned p2 = g_itemoff[col] + atomicAdd(&g_cursor[col], 1u);
    g_items[p2] = (((unsigned long long)row) << 22) | (2ull << 20) | (unsigned)e;
}

// ---------- 6. warp-per-node register rank-sort + vectorized expansion ----------
__global__ void __launch_bounds__(256) k_sort_expand(float* __restrict__ out, int n, size_t M) {
    __shared__ unsigned long long skeys[8][64];
    int warp = (int)threadIdx.x >> 5;
    int lane = (int)threadIdx.x & 31;
    int wi   = blockIdx.x * 8 + warp;
    if (wi >= n) return;

    if (lane == 0) g_deg[wi] = 0u;     // restore zero-invariant

    unsigned beg = g_itemoff[wi];
    unsigned end = g_itemoff[wi + 1];
    int cnt = (int)(end - beg);

    float* idx0 = out;
    float* idx1 = out + M;
    float* vals = out + 2 * M;
    size_t nodebase = (size_t)beg * 16;
    int fourcnt = cnt << 2;
    float fbase = (float)(wi << 2);

    if (cnt <= 64) {
        unsigned long long* sk = skeys[warp];
        // register rank-sort: each lane holds <=2 keys, exact rank via shfl broadcast
        unsigned long long k0 = (lane < cnt)      ? g_items[beg + lane]      : ~0ull;
        unsigned long long k1 = (lane + 32 < cnt) ? g_items[beg + lane + 32] : ~0ull;
        int r0 = 0, r1 = 0;
#pragma unroll
        for (int s = 0; s < 32; s++) {
            unsigned long long o0 = __shfl_sync(0xFFFFFFFFu, k0, s);
            unsigned long long o1 = __shfl_sync(0xFFFFFFFFu, k1, s);
            r0 += (int)(o0 < k0) + (int)(o1 < k0);
            r1 += (int)(o0 < k1) + (int)(o1 < k1);
        }
        if (lane < cnt)      sk[r0] = k0;
        if (lane + 32 < cnt) sk[r1] = k1;
        __syncwarp();

        // item-owner expansion: lane processes items t = lane, lane+32
#pragma unroll
        for (int half = 0; half < 2; half++) {
            int t = lane + half * 32;
            if (t >= cnt) break;
            unsigned long long key = sk[t];
            unsigned tgt = (unsigned)(key >> 22);
            unsigned cls = ((unsigned)(key >> 20)) & 3u;
            unsigned e   = (unsigned)key & 0xFFFFFu;

            // equal-target run (rare: len>1 only on target collisions)
            int g0 = t; while (g0 > 0 && (unsigned)(sk[g0 - 1] >> 22) == tgt) g0--;
            int g1 = t; while (g1 + 1 < cnt && (unsigned)(sk[g1 + 1] >> 22) == tgt) g1++;
            int len = g1 - g0 + 1;

            const float4* src = (cls == 0)
                ? reinterpret_cast<const float4*>(&g_diag[(size_t)wi << 4])
                : reinterpret_cast<const float4*>(&g_P[(size_t)e << 4]);
            float4 m0 = src[0], m1 = src[1], m2 = src[2], m3 = src[3];

            float4 V0, V1, V2, V3;
            if (cls == 0) {            // symmetric reconstruction from upper triangle
                V0 = m0;
                V1 = make_float4(m0.y, m1.y, m1.z, m1.w);
                V2 = make_float4(m0.z, m1.z, m2.z, m2.w);
                V3 = make_float4(m0.w, m1.w, m2.w, m3.w);
            } else if (cls == 1) {     // -P
                V0 = make_float4(-m0.x, -m0.y, -m0.z, -m0.w);
                V1 = make_float4(-m1.x, -m1.y, -m1.z, -m1.w);
                V2 = make_float4(-m2.x, -m2.y, -m2.z, -m2.w);
                V3 = make_float4(-m3.x, -m3.y, -m3.z, -m3.w);
            } else {                   // -P^T
                V0 = make_float4(-m0.x, -m1.x, -m2.x, -m3.x);
                V1 = make_float4(-m0.y, -m1.y, -m2.y, -m3.y);
                V2 = make_float4(-m0.z, -m1.z, -m2.z, -m3.z);
                V3 = make_float4(-m0.w, -m1.w, -m2.w, -m3.w);
            }

            float tj = (float)(tgt << 2);
            if (len == 1) {
                float4 j4 = make_float4(tj, tj + 1.f, tj + 2.f, tj + 3.f);
#pragma unroll
                for (int a = 0; a < 4; a++) {
                    size_t pos = nodebase + (size_t)a * fourcnt + (t << 2);
                    float fi = fbase + (float)a;
                    *reinterpret_cast<float4*>(idx0 + pos) = make_float4(fi, fi, fi, fi);
                    *reinterpret_cast<float4*>(idx1 + pos) = j4;
                    float4 V = (a == 0) ? V0 : (a == 1) ? V1 : (a == 2) ? V2 : V3;
                    *reinterpret_cast<float4*>(vals + pos) = V;
                }
            } else {
                int base = (g0 << 2) + (t - g0);
#pragma unroll
                for (int a = 0; a < 4; a++) {
                    size_t rb = nodebase + (size_t)a * fourcnt + base;
                    float fi = fbase + (float)a;
                    float4 V = (a == 0) ? V0 : (a == 1) ? V1 : (a == 2) ? V2 : V3;
                    float vb[4] = {V.x, V.y, V.z, V.w};
#pragma unroll
                    for (int b = 0; b < 4; b++) {
                        size_t pos = rb + (size_t)b * len;
                        idx0[pos] = fi;
                        idx1[pos] = tj + (float)b;
                        vals[pos] = vb[b];
                    }
                }
            }
        }
    } else {
        // cold fallback: O(cnt^2) rank sort via global, scalar expansion
        for (int jj = lane; jj < cnt; jj += 32) {
            unsigned long long kj = g_items[beg + jj];
            int rk = 0;
            for (int k2 = 0; k2 < cnt; k2++) rk += (g_items[beg + k2] < kj);
            g_items2[beg + rk] = kj;
        }
        __syncwarp();
        const unsigned long long* keys = &g_items2[beg];
#pragma unroll
        for (int a = 0; a < 4; a++) {
            float fi = fbase + (float)a;
            size_t rowbase = nodebase + (size_t)a * fourcnt;
            int aoff = a << 2;
            for (int r = lane; r < fourcnt; r += 32) {
                int t = r >> 2, b = r & 3;
                unsigned long long key = keys[t];
                unsigned tgt = (unsigned)(key >> 22);
                unsigned cls = ((unsigned)(key >> 20)) & 3u;
                unsigned e   = (unsigned)key & 0xFFFFFu;
                int g0 = t; while (g0 > 0 && (unsigned)(keys[g0 - 1] >> 22) == tgt) g0--;
                int g1 = t; while (g1 + 1 < cnt && (unsigned)(keys[g1 + 1] >> 22) == tgt) g1++;
                int len = g1 - g0 + 1;
                int posrow = (g0 << 2) + b * len + (t - g0);
                float v;
                if (cls == 0) {
                    int lo = a < b ? a : b, hi = a < b ? b : a;  // symmetric
                    v = g_diag[((size_t)wi << 4) + lo * 4 + hi];
                } else if (cls == 1) v = -g_P[((size_t)e << 4) + aoff + b];
                else                 v = -g_P[((size_t)e << 4) + (b << 2) + a];
                size_t pos = rowbase + posrow;
                idx0[pos] = fi;
                idx1[pos] = (float)((tgt << 2) + b);
                vals[pos] = v;
            }
        }
    }
}

extern "C" void kernel_launch(void* const* d_in, const int* in_sizes, int n_in,
                              void* d_out, int out_size) {
    const float* maps = (const float*)d_in[0];
    const int*   ei   = (const int*)d_in[1];

    int twoE = in_sizes[0] / 16;
    int E    = twoE / 2;
    size_t M = (size_t)out_size / 3;
    int n    = (int)((M - (size_t)twoE * 16) / 16);
    int nb   = (n + 1023) / 1024;

    float* out = (float*)d_out;
    const int B = 256;

    k_deg        <<<(E + B - 1) / B, B>>>(ei, E, twoE);
    k_scan_blocks<<<nb, 1024>>>(n);
    k_scan_tot   <<<1, NB_MAX>>>(nb, n);
    k_finalize   <<<(n + B - 1) / B, B>>>(n);
    k_edge_all   <<<(E + B - 1) / B, B>>>(maps, ei, E, twoE);
    k_sort_expand<<<(n + 7) / 8, 256>>>(out, n, M);
}